// round 7
// baseline (speedup 1.0000x reference)
#include <cuda_runtime.h>
#include <cuda_fp16.h>

// LSTMPredictor: B=256, T=1024, HID=150, input dim 1, future=0.
// R7: 128 CTAs x 608 threads (19 warps), 2 batches per CTA.
// Weights fp16 in smem in a LANE-LINEAR layout: slot(chunk,row) x tid, so
// every LDS.128 is conflict-free by construction (each 8-lane phase group
// reads one aligned 128B line). Thread quad 4j..4j+3 owns hidden unit j:
//   sub 0/1 = (i_j,g_j) over K-halves,  sub 2/3 = (f_j,o_j) over K-halves.
// shfl_xor(1) combines the K split, shfl_xor(2) delivers a=sig(i)tanh(g)
// to the (f,o) lanes; sub2 updates batch0 cell/h, sub3 batch1.
// One __syncthreads per step; ping-pong h; out[t-1] retimed.

namespace {

constexpr int HID  = 150;
constexpr int TT   = 1024;
constexpr int NCTA = 128;
constexpr int NTHR = 608;
constexpr int NCL  = 10;    // 16B K-chunks per thread (K-half)
constexpr int CGN  = 20;    // total 16B chunks per padded row (160 halves)
constexpr int RPH  = 160;   // padded h row length in halves

// Shared memory layout (bytes)
constexpr int OFF_W    = 0;                         // fp16 weights, lane-linear:
                                                    // ((cl*2+r)*608 + tid)*16
                                                    // = 20*608*16 = 194560
constexpr int OFF_HK   = 194560;                    // fp16 h [2buf][2b][160] = 1280
constexpr int OFF_HBUF = 195840;                    // fp32 h [2buf][2b][160] = 5120
constexpr int OFF_WLIN = 200960;                    // fp32 [160] = 640
constexpr int OFF_XIN  = 201600;                    // fp32 [2][1024] = 8192
constexpr int SMEM_BYTES = 209792;                  // ~204.9 KB (< 227 KB)

__device__ __forceinline__ float sigf(float x) {
    return __fdividef(1.0f, 1.0f + __expf(-x));
}
__device__ __forceinline__ float tanhfast(float x) {
    return 1.0f - __fdividef(2.0f, __expf(2.0f * x) + 1.0f);
}

} // namespace

__global__ void __launch_bounds__(NTHR, 1)
lstm_pred_kernel(const float* __restrict__ input,   // [256][1024]
                 const float* __restrict__ W_ih,    // [600][1]
                 const float* __restrict__ W_hh,    // [600][150]
                 const float* __restrict__ b_ih,    // [600]
                 const float* __restrict__ b_hh,    // [600]
                 const float* __restrict__ W_lin,   // [1][150]
                 const float* __restrict__ b_lin,   // [1]
                 float* __restrict__ out)           // [256][1024]
{
    extern __shared__ char smem[];
    uint4*  wsm    = reinterpret_cast<uint4*>(smem + OFF_W);
    __half* hk     = reinterpret_cast<__half*>(smem + OFF_HK);
    float*  hbuf   = reinterpret_cast<float*>(smem + OFF_HBUF);
    float*  wlin_s = reinterpret_cast<float*>(smem + OFF_WLIN);
    float*  xin    = reinterpret_cast<float*>(smem + OFF_XIN);

    const int tid = threadIdx.x;
    const int b0  = blockIdx.x * 2;

    const int  j    = ((tid < 600) ? tid : 596) >> 2;  // hidden unit 0..149
    const int  sub  = tid & 3;        // 0/1: (i,g) K-halves; 2/3: (f,o)
    const int  bsel = tid & 1;        // K-half; also batch select in tails
    const bool act  = (tid < 600);
    const int  rA   = j + (sub >= 2 ? HID : 0);        // i_j or f_j
    const int  rB   = rA + 2 * HID;                    // g_j or o_j

    // ---- one-time init ----
    for (int i = tid; i < HID; i += NTHR) wlin_s[i] = W_lin[i];
    for (int i = tid; i < 2 * 2 * RPH; i += NTHR) hk[i] = __half(0);
    for (int i = tid; i < 2 * TT; i += NTHR)
        xin[i] = input[(b0 + (i >> 10)) * TT + (i & (TT - 1))];

    // Gather this thread's weight chunks into its lane-linear slots.
    {
        const float* gA = W_hh + rA * HID;
        const float* gB = W_hh + rB * HID;
        for (int cl = 0; cl < NCL; ++cl) {
            const int k0 = (bsel * NCL + cl) * 8;      // first half index
            __half2 pk[2][4];
#pragma unroll
            for (int m = 0; m < 4; ++m) {
                const int k = k0 + 2 * m;
                const float a0 = (k < HID) ? gA[k] : 0.f;
                const float a1 = (k + 1 < HID) ? gA[k + 1] : 0.f;
                const float e0 = (k < HID) ? gB[k] : 0.f;
                const float e1 = (k + 1 < HID) ? gB[k + 1] : 0.f;
                pk[0][m] = __floats2half2_rn(a0, a1);
                pk[1][m] = __floats2half2_rn(e0, e1);
            }
            wsm[(cl * 2 + 0) * NTHR + tid] = *reinterpret_cast<uint4*>(pk[0]);
            wsm[(cl * 2 + 1) * NTHR + tid] = *reinterpret_cast<uint4*>(pk[1]);
        }
    }

    const float wihA  = act ? W_ih[rA] : 0.f;
    const float wihB  = act ? W_ih[rB] : 0.f;
    const float biasA = act ? (b_ih[rA] + b_hh[rA]) : 0.f;
    const float biasB = act ? (b_ih[rB] + b_hh[rB]) : 0.f;
    float cst = 0.f;                       // cell state (sub>=2; bsel batch)
    const float blin = b_lin[0];

    const uint4* hku = reinterpret_cast<const uint4*>(hk);  // 40 u4 per buf
    const uint4* wp  = wsm + tid;          // stride 2*NTHR per chunk, +NTHR rB
    const int cg0 = bsel * NCL;            // this lane's first h chunk

    __syncthreads();

    for (int t = 0; t < TT; ++t) {
        const int cur = t & 1;
        const int nxt = cur ^ 1;

        // ---- retimed output: out[t-1] from hbuf[cur], warps 0-1 ----
        if (t && tid < 64) {
            const int bb   = tid >> 5;
            const int lane = tid & 31;
            const float* hb = hbuf + cur * 2 * RPH + bb * RPH;
            float s = 0.f;
#pragma unroll
            for (int m = 0; m < 5; ++m) {
                const int jj = lane + 32 * m;
                if (jj < HID) s = fmaf(hb[jj], wlin_s[jj], s);
            }
#pragma unroll
            for (int off = 16; off; off >>= 1)
                s += __shfl_down_sync(0xffffffffu, s, off);
            if (lane == 0) out[(b0 + bb) * TT + (t - 1)] = s + blin;
        }

        // ---- dot phase over this lane's K-half, distance-1 prefetch ----
        const uint4* h0v = hku + cur * 2 * CGN;      // batch0 chunks
        const uint4* h1v = h0v + CGN;                // batch1 chunks
        const __half2 z = __float2half2_rn(0.f);
        __half2 aA0 = z, aA1 = z, aB0 = z, aB1 = z;
        float gA0 = 0.f, gA1 = 0.f, gB0 = 0.f, gB1 = 0.f;

        uint4 wa = wp[0], wb = wp[NTHR];
        uint4 u0 = h0v[cg0], u1 = h1v[cg0];
#pragma unroll
        for (int cl = 0; cl < NCL; ++cl) {
            uint4 wan, wbn, n0, n1;
            if (cl < NCL - 1) {
                wan = wp[(cl + 1) * 2 * NTHR];
                wbn = wp[(cl + 1) * 2 * NTHR + NTHR];
                n0  = h0v[cg0 + cl + 1];
                n1  = h1v[cg0 + cl + 1];
            }
            const __half2* wAh = reinterpret_cast<const __half2*>(&wa);
            const __half2* wBh = reinterpret_cast<const __half2*>(&wb);
            const __half2* h0h = reinterpret_cast<const __half2*>(&u0);
            const __half2* h1h = reinterpret_cast<const __half2*>(&u1);
#pragma unroll
            for (int m = 0; m < 4; ++m) {
                aA0 = __hfma2(wAh[m], h0h[m], aA0);
                aA1 = __hfma2(wAh[m], h1h[m], aA1);
                aB0 = __hfma2(wBh[m], h0h[m], aB0);
                aB1 = __hfma2(wBh[m], h1h[m], aB1);
            }
            if (cl == 4 || cl == NCL - 1) {           // fp32 flush (40 halves)
                float2 f;
                f = __half22float2(aA0); gA0 += f.x + f.y; aA0 = z;
                f = __half22float2(aA1); gA1 += f.x + f.y; aA1 = z;
                f = __half22float2(aB0); gB0 += f.x + f.y; aB0 = z;
                f = __half22float2(aB1); gB1 += f.x + f.y; aB1 = z;
            }
            wa = wan; wb = wbn; u0 = n0; u1 = n1;
        }

        // ---- combine K halves within (gate) lane pair ----
        gA0 += __shfl_xor_sync(0xffffffffu, gA0, 1);
        gA1 += __shfl_xor_sync(0xffffffffu, gA1, 1);
        gB0 += __shfl_xor_sync(0xffffffffu, gB0, 1);
        gB1 += __shfl_xor_sync(0xffffffffu, gB1, 1);

        const float x0 = xin[t], x1 = xin[TT + t];
        gA0 += fmaf(x0, wihA, biasA);
        gA1 += fmaf(x1, wihA, biasA);
        gB0 += fmaf(x0, wihB, biasB);
        gB1 += fmaf(x1, wihB, biasB);

        // (i,g) lanes: this lane's batch activation a = sig(i)*tanh(g)
        float a_mine = 0.f;
        if (sub < 2) {
            const float gi = bsel ? gA1 : gA0;
            const float gg = bsel ? gB1 : gB0;
            a_mine = sigf(gi) * tanhfast(gg);
        }
        const float a_recv = __shfl_xor_sync(0xffffffffu, a_mine, 2);

        // (f,o) lanes: finish cell update for their batch, write h_t
        if (act && sub >= 2) {
            const float gf = bsel ? gA1 : gA0;
            const float go = bsel ? gB1 : gB0;
            cst = fmaf(sigf(gf), cst, a_recv);
            const float hn = sigf(go) * tanhfast(cst);
            hbuf[nxt * 2 * RPH + bsel * RPH + j] = hn;
            hk[nxt * 2 * RPH + bsel * RPH + j]   = __float2half(hn);
        }
        __syncthreads();
    }

    // ---- epilogue: out[TT-1] ----
    if (tid < 64) {
        const int bb   = tid >> 5;
        const int lane = tid & 31;
        const float* hb = hbuf + (TT & 1) * 2 * RPH + bb * RPH;
        float s = 0.f;
#pragma unroll
        for (int m = 0; m < 5; ++m) {
            const int jj = lane + 32 * m;
            if (jj < HID) s = fmaf(hb[jj], wlin_s[jj], s);
        }
#pragma unroll
        for (int off = 16; off; off >>= 1)
            s += __shfl_down_sync(0xffffffffu, s, off);
        if (lane == 0) out[(b0 + bb) * TT + (TT - 1)] = s + blin;
    }
}

extern "C" void kernel_launch(void* const* d_in, const int* in_sizes, int n_in,
                              void* d_out, int out_size) {
    const float* input = (const float*)d_in[0];
    const float* W_ih  = (const float*)d_in[1];
    const float* W_hh  = (const float*)d_in[2];
    const float* b_ih  = (const float*)d_in[3];
    const float* b_hh  = (const float*)d_in[4];
    const float* W_lin = (const float*)d_in[5];
    const float* b_lin = (const float*)d_in[6];
    float* out = (float*)d_out;

    cudaFuncSetAttribute(lstm_pred_kernel,
                         cudaFuncAttributeMaxDynamicSharedMemorySize, SMEM_BYTES);
    lstm_pred_kernel<<<NCTA, NTHR, SMEM_BYTES>>>(input, W_ih, W_hh, b_ih, b_hh,
                                                 W_lin, b_lin, out);
}

// round 9
// speedup vs baseline: 2.1180x; 2.1180x over previous
#include <cuda_runtime.h>
#include <cuda_fp16.h>
#include <cstdint>

// LSTMPredictor B=256,T=1024,HID=150 — R9: warp-level HMMA (mma.sync,
// m16n8k16, fp16 in / fp32 acc), compiles for plain sm_100 (no tcgen05).
// 128 CTAs x 256 threads (8 warps), 2 batches/CTA (N=8 tile, cols 0,1 real).
// Per step: D[640x8] = W_hh x h. Warp w owns M-tiles {w+8i, i<5}: tiles
// i<4 have A fragments pinned in REGISTERS for all 1024 steps (zero weight
// traffic); tile i=4's fragments sit in lane-linear smem (conflict-free
// LDS.128). B fragments built from fp16 h[8][168] with conflict-free LDS.32.
// Gate rows (i,f,g,o) = (j, 150+j, 300+j, 450+j); 150 update threads.

namespace {

constexpr int HID = 150, TT = 1024, NCTA = 128, NTHR = 256, NW = 8;
constexpr int KT = 10;            // K-tiles of 16 (K padded to 160)
constexpr int HKP = 168;          // h pitch in halves (84 words: bank-clean)

// dynamic smem offsets (bytes)
constexpr int OFF_HK   = 0;                 // fp16 h [8][168] = 2688
constexpr int OFF_HBUF = 2688;              // fp32 h [2][152] = 1216
constexpr int OFF_G2   = 3904;              // float2 gates [640] = 5120
constexpr int OFF_WLIN = 9024;              // fp32 [160] = 640
constexpr int OFF_W5   = 9664;              // uint4 A-frags tile i=4:
                                            // 8 w * 10 kt * 32 lanes * 16B = 40960
constexpr int OFF_XIN  = 50624;             // fp32 [2][1024] = 8192
constexpr int SMEM_BYTES = 58816;

__device__ __forceinline__ float sigf(float x) {
    return __fdividef(1.0f, 1.0f + __expf(-x));
}
__device__ __forceinline__ float tanhfast(float x) {
    return 1.0f - __fdividef(2.0f, __expf(2.0f * x) + 1.0f);
}

__device__ __forceinline__ void mma16816(float& d0, float& d1, float& d2,
                                         float& d3, uint32_t a0, uint32_t a1,
                                         uint32_t a2, uint32_t a3,
                                         uint32_t b0, uint32_t b1) {
    asm volatile(
        "mma.sync.aligned.m16n8k16.row.col.f32.f16.f16.f32 "
        "{%0,%1,%2,%3}, {%4,%5,%6,%7}, {%8,%9}, {%0,%1,%2,%3};"
        : "+f"(d0), "+f"(d1), "+f"(d2), "+f"(d3)
        : "r"(a0), "r"(a1), "r"(a2), "r"(a3), "r"(b0), "r"(b1));
}

// W_hh element with zero padding (rows >= 600, cols >= 150)
__device__ __forceinline__ float wel(const float* W, int r, int c) {
    return (r < 600 && c < HID) ? W[r * HID + c] : 0.f;
}
__device__ __forceinline__ uint32_t h2u(__half2 v) {
    return *reinterpret_cast<uint32_t*>(&v);
}

} // namespace

__global__ void __launch_bounds__(NTHR, 1)
lstm_hmma_kernel(const float* __restrict__ input,   // [256][1024]
                 const float* __restrict__ W_ih,    // [600][1]
                 const float* __restrict__ W_hh,    // [600][150]
                 const float* __restrict__ b_ih,    // [600]
                 const float* __restrict__ b_hh,    // [600]
                 const float* __restrict__ W_lin,   // [1][150]
                 const float* __restrict__ b_lin,   // [1]
                 float* __restrict__ out)           // [256][1024]
{
    extern __shared__ char smem[];
    __half* hk     = reinterpret_cast<__half*>(smem + OFF_HK);
    float*  hbuf   = reinterpret_cast<float*>(smem + OFF_HBUF);
    float2* g2     = reinterpret_cast<float2*>(smem + OFF_G2);
    float*  wlin_s = reinterpret_cast<float*>(smem + OFF_WLIN);
    uint4*  w5     = reinterpret_cast<uint4*>(smem + OFF_W5);
    float*  xin    = reinterpret_cast<float*>(smem + OFF_XIN);

    const int tid  = threadIdx.x;
    const int wid  = tid >> 5;
    const int lane = tid & 31;
    const int g    = lane >> 2;      // fragment row-group 0..7
    const int tig  = lane & 3;       // thread-in-group
    const int b0   = blockIdx.x * 2;

    // ---- one-time init ----
    for (int i = tid; i < 8 * HKP; i += NTHR) hk[i] = __half(0);
    for (int i = tid; i < 2 * 152; i += NTHR) hbuf[i] = 0.f;
    for (int i = tid; i < HID; i += NTHR) wlin_s[i] = W_lin[i];
    for (int i = tid; i < 2 * TT; i += NTHR)
        xin[i] = input[(b0 + (i >> 10)) * TT + (i & (TT - 1))];

    // A fragments: m16n8k16 .row layout. mtile = wid + 8*i.
    uint32_t af[4][KT][4];
#pragma unroll
    for (int i = 0; i < 5; ++i) {
        const int mb = 16 * (wid + 8 * i);
#pragma unroll
        for (int kt = 0; kt < KT; ++kt) {
            const int kb = 16 * kt + 2 * tig;
            const int r0 = mb + g, r1 = mb + g + 8;
            uint32_t f0 = h2u(__floats2half2_rn(wel(W_hh, r0, kb),
                                                wel(W_hh, r0, kb + 1)));
            uint32_t f1 = h2u(__floats2half2_rn(wel(W_hh, r1, kb),
                                                wel(W_hh, r1, kb + 1)));
            uint32_t f2 = h2u(__floats2half2_rn(wel(W_hh, r0, kb + 8),
                                                wel(W_hh, r0, kb + 9)));
            uint32_t f3 = h2u(__floats2half2_rn(wel(W_hh, r1, kb + 8),
                                                wel(W_hh, r1, kb + 9)));
            if (i < 4) {
                af[i][kt][0] = f0; af[i][kt][1] = f1;
                af[i][kt][2] = f2; af[i][kt][3] = f3;
            } else {
                w5[(wid * KT + kt) * 32 + lane] = make_uint4(f0, f1, f2, f3);
            }
        }
    }

    // Update-thread constants (gate rows j, 150+j, 300+j, 450+j)
    float wih[4], bia[4];
    if (tid < HID) {
#pragma unroll
        for (int r = 0; r < 4; ++r) {
            const int row = r * HID + tid;
            wih[r] = W_ih[row];
            bia[r] = b_ih[row] + b_hh[row];
        }
    }
    float c0 = 0.f, c1 = 0.f;
    const float blin = b_lin[0];

    __syncthreads();

    for (int t = 0; t < TT; ++t) {
        // ---- overlapped output: out[t-1] from hbuf = h_{t-1} (warps 4,5) ----
        if (t && (wid == 4 || wid == 5)) {
            const int bb = wid - 4;
            float s = 0.f;
#pragma unroll
            for (int m = 0; m < 5; ++m) {
                const int jj = lane + 32 * m;
                if (jj < HID) s = fmaf(hbuf[bb * 152 + jj], wlin_s[jj], s);
            }
#pragma unroll
            for (int off = 16; off; off >>= 1)
                s += __shfl_down_sync(0xffffffffu, s, off);
            if (lane == 0) out[(b0 + bb) * TT + (t - 1)] = s + blin;
        }

        // ---- B fragments from h_{t-1} (conflict-free LDS.32) ----
        uint32_t bf[KT][2];
#pragma unroll
        for (int kt = 0; kt < KT; ++kt) {
            const int base = g * HKP + 16 * kt + 2 * tig;
            bf[kt][0] = *reinterpret_cast<const uint32_t*>(hk + base);
            bf[kt][1] = *reinterpret_cast<const uint32_t*>(hk + base + 8);
        }

        // ---- 5 M-tiles x 10 K-tiles of HMMA ----
#pragma unroll
        for (int i = 0; i < 5; ++i) {
            float d0 = 0.f, d1 = 0.f, d2 = 0.f, d3 = 0.f;
            if (i < 4) {
#pragma unroll
                for (int kt = 0; kt < KT; ++kt)
                    mma16816(d0, d1, d2, d3, af[i][kt][0], af[i][kt][1],
                             af[i][kt][2], af[i][kt][3], bf[kt][0], bf[kt][1]);
            } else {
#pragma unroll
                for (int kt = 0; kt < KT; ++kt) {
                    const uint4 q = w5[(wid * KT + kt) * 32 + lane];
                    mma16816(d0, d1, d2, d3, q.x, q.y, q.z, q.w,
                             bf[kt][0], bf[kt][1]);
                }
            }
            if (tig == 0) {           // cols 0,1 live in these lanes
                const int mb = 16 * (wid + 8 * i);
                g2[mb + g]     = make_float2(d0, d1);
                g2[mb + 8 + g] = make_float2(d2, d3);
            }
        }
        __syncthreads();              // gates ready; hk reads complete

        // ---- pointwise LSTM update: thread j < 150 ----
        if (tid < HID) {
            const int j = tid;
            const float x0 = xin[t], x1 = xin[TT + t];
            float2 gi = g2[j],        gf = g2[HID + j];
            float2 gg = g2[2*HID + j], go = g2[3*HID + j];
            gi.x += fmaf(x0, wih[0], bia[0]); gi.y += fmaf(x1, wih[0], bia[0]);
            gf.x += fmaf(x0, wih[1], bia[1]); gf.y += fmaf(x1, wih[1], bia[1]);
            gg.x += fmaf(x0, wih[2], bia[2]); gg.y += fmaf(x1, wih[2], bia[2]);
            go.x += fmaf(x0, wih[3], bia[3]); go.y += fmaf(x1, wih[3], bia[3]);
            c0 = fmaf(sigf(gf.x), c0, sigf(gi.x) * tanhfast(gg.x));
            c1 = fmaf(sigf(gf.y), c1, sigf(gi.y) * tanhfast(gg.y));
            const float h0 = sigf(go.x) * tanhfast(c0);
            const float h1 = sigf(go.y) * tanhfast(c1);
            hbuf[j]       = h0;
            hbuf[152 + j] = h1;
            hk[j]         = __float2half(h0);   // B rows n=0,1; n>=2 stay 0
            hk[HKP + j]   = __float2half(h1);
        }
        __syncthreads();              // h_t visible for next step
    }

    // ---- epilogue: out[TT-1] ----
    if (wid == 4 || wid == 5) {
        const int bb = wid - 4;
        float s = 0.f;
#pragma unroll
        for (int m = 0; m < 5; ++m) {
            const int jj = lane + 32 * m;
            if (jj < HID) s = fmaf(hbuf[bb * 152 + jj], wlin_s[jj], s);
        }
#pragma unroll
        for (int off = 16; off; off >>= 1)
            s += __shfl_down_sync(0xffffffffu, s, off);
        if (lane == 0) out[(b0 + bb) * TT + (TT - 1)] = s + blin;
    }
}

extern "C" void kernel_launch(void* const* d_in, const int* in_sizes, int n_in,
                              void* d_out, int out_size) {
    const float* input = (const float*)d_in[0];
    const float* W_ih  = (const float*)d_in[1];
    const float* W_hh  = (const float*)d_in[2];
    const float* b_ih  = (const float*)d_in[3];
    const float* b_hh  = (const float*)d_in[4];
    const float* W_lin = (const float*)d_in[5];
    const float* b_lin = (const float*)d_in[6];
    float* out = (float*)d_out;

    cudaFuncSetAttribute(lstm_hmma_kernel,
                         cudaFuncAttributeMaxDynamicSharedMemorySize, SMEM_BYTES);
    lstm_hmma_kernel<<<NCTA, NTHR, SMEM_BYTES>>>(input, W_ih, W_hh, b_ih, b_hh,
                                                 W_lin, b_lin, out);
}